// round 12
// baseline (speedup 1.0000x reference)
#include <cuda_runtime.h>
#include <cuda_bf16.h>
#include <math.h>

#define NUM_SEG 16
#define CHAN 128
#define HID 32

// Pass-1: 128 thr (4 warps), ~33KB smem -> 6 blocks/SM. Single full wave.
#define NBLK1 888          // 148 SMs * 6 blocks
#define THR1 128

// Modulate: 8 blocks/SM single wave
#define NBLK3 1184
#define THR3 256

// Zero-initialized at module load; the LAST modulate block re-zeroes after
// all blocks consumed g_sum/g_cnt, so the zero invariant holds across every
// graph replay (same work every call).
__device__ float g_sum[NUM_SEG * CHAN];   // atomic accumulators
__device__ float g_cnt[NUM_SEG];          // atomic count accumulators
__device__ int   g_ticket;                // modulate completion ticket

// ---- packed f32x2 helpers (sm_103a) --------------------------------------
__device__ __forceinline__ unsigned long long fadd2(unsigned long long a,
                                                    unsigned long long b) {
    unsigned long long r;
    asm("add.rn.f32x2 %0, %1, %2;" : "=l"(r) : "l"(a), "l"(b));
    return r;
}
__device__ __forceinline__ unsigned long long fmul2(unsigned long long a,
                                                    unsigned long long b) {
    unsigned long long r;
    asm("mul.rn.f32x2 %0, %1, %2;" : "=l"(r) : "l"(a), "l"(b));
    return r;
}

struct F4 { unsigned long long lo, hi; };  // float4 as 2x f32x2

__device__ __forceinline__ F4 ld_f4_cs(const F4* p) {
    F4 r;
    asm("ld.global.cs.v4.b32 {%0,%1,%2,%3}, [%4];"
        : "=r"(((unsigned*)&r)[0]), "=r"(((unsigned*)&r)[1]),
          "=r"(((unsigned*)&r)[2]), "=r"(((unsigned*)&r)[3])
        : "l"(p));
    return r;
}

__device__ __forceinline__ void rmw(F4* buf, int s, int lane, F4 v) {
    F4* p = buf + s * 32 + lane;
    F4 a = *p;
    a.lo = fadd2(a.lo, v.lo);
    a.hi = fadd2(a.hi, v.hi);
    *p = a;
}

// ---------------------------------------------------------------------------
// Kernel 1: segment sums (at its L1tex/DRAM co-limit ~12 wf/row). Epilogue:
// combine the 4 warp-private regions, then RED (atomicAdd, no return) the
// 2048 floats straight into g_sum — no partial buffer round-trip.
// ---------------------------------------------------------------------------
__global__ void __launch_bounds__(THR1) seg_sum_kernel(
    const float* __restrict__ x, const int* __restrict__ idx, int N)
{
    __shared__ F4 s_acc[4 * NUM_SEG * 32];   // 32KB
    __shared__ float s_cnt[4 * NUM_SEG];

    const int tid  = threadIdx.x;
    const int lane = tid & 31;
    const int w    = tid >> 5;

    F4* buf = s_acc + w * (NUM_SEG * 32);

    for (int i = tid; i < 4 * NUM_SEG * 32; i += THR1) {
        s_acc[i].lo = 0ull; s_acc[i].hi = 0ull;
    }
    __syncthreads();

    const int gw = blockIdx.x * 4 + w;   // global warp id
    const int NW = NBLK1 * 4;            // total warps
    const F4* X = (const F4*)x;
    const int ngroups = N >> 3;          // groups of 8 rows

    int cnt = 0;
    for (int g = gw; g < ngroups; g += NW) {
        const int base = g << 3;
        int4 i0 = __ldg((const int4*)(idx + base));
        int4 i1 = __ldg((const int4*)(idx + base + 4));
        const size_t o = (size_t)base * 32 + lane;
        F4 v0 = ld_f4_cs(X + o);
        F4 v1 = ld_f4_cs(X + o + 32);
        F4 v2 = ld_f4_cs(X + o + 64);
        F4 v3 = ld_f4_cs(X + o + 96);
        F4 v4 = ld_f4_cs(X + o + 128);
        F4 v5 = ld_f4_cs(X + o + 160);
        F4 v6 = ld_f4_cs(X + o + 192);
        F4 v7 = ld_f4_cs(X + o + 224);

        cnt += (i0.x == lane) + (i0.y == lane) + (i0.z == lane) + (i0.w == lane)
             + (i1.x == lane) + (i1.y == lane) + (i1.z == lane) + (i1.w == lane);

        rmw(buf, i0.x, lane, v0);
        rmw(buf, i0.y, lane, v1);
        rmw(buf, i0.z, lane, v2);
        rmw(buf, i0.w, lane, v3);
        rmw(buf, i1.x, lane, v4);
        rmw(buf, i1.y, lane, v5);
        rmw(buf, i1.z, lane, v6);
        rmw(buf, i1.w, lane, v7);
    }
    // tail (N not multiple of 8)
    for (int r = (ngroups << 3) + gw; r < N; r += NW) {
        int s = __ldg(idx + r);
        F4 v = ld_f4_cs(X + (size_t)r * 32 + lane);
        cnt += (s == lane);
        rmw(buf, s, lane, v);
    }

    if (lane < NUM_SEG) s_cnt[w * NUM_SEG + lane] = (float)cnt;
    __syncthreads();

    // Combine 4 warp regions -> RED into g_sum (layout [seg*128 + chan]).
    const float* sa = (const float*)s_acc;
    const int R = NUM_SEG * CHAN;  // 2048 floats per region
    #pragma unroll 4
    for (int i = tid; i < R; i += THR1) {
        float v = sa[i] + sa[R + i] + sa[2 * R + i] + sa[3 * R + i];
        atomicAdd(&g_sum[i], v);
    }
    if (tid < NUM_SEG) {
        float c = s_cnt[tid] + s_cnt[NUM_SEG + tid] +
                  s_cnt[2 * NUM_SEG + tid] + s_cnt[3 * NUM_SEG + tid];
        atomicAdd(&g_cnt[tid], c);
    }
}

// ---------------------------------------------------------------------------
// Kernel 2 (fused): each block recomputes the tiny SE-MLP gate table from
// g_sum/g_cnt as a prologue (~512 FMA/thread, weights hot in L2), then
// streams out = x * gate[idx]. The block drawing the LAST ticket zeroes the
// accumulators, restoring the replay invariant (strictly after all reads).
// ---------------------------------------------------------------------------
__global__ void __launch_bounds__(THR3) modulate_kernel(
    const float* __restrict__ x, const int* __restrict__ idx,
    const float* __restrict__ W1, const float* __restrict__ W2,
    float* __restrict__ out, int N)
{
    __shared__ float s_pool[NUM_SEG * CHAN];   // 8KB pooled means
    __shared__ float s_h[NUM_SEG * HID];       // 2KB hidden
    __shared__ float s_gatef[NUM_SEG * CHAN];  // 8KB gate (float view)
    __shared__ float s_c[NUM_SEG];
    __shared__ int   s_last;

    const int tid = threadIdx.x;

    // --- prologue: gate = sigmoid(W2 @ relu(W1 @ pooled)) ---
    if (tid < NUM_SEG) s_c[tid] = fmaxf(g_cnt[tid], 1.0f);
    __syncthreads();
    for (int i = tid; i < NUM_SEG * CHAN; i += THR3)
        s_pool[i] = g_sum[i] / s_c[i >> 7];
    __syncthreads();

    // h: 512 values, 2 per thread (dot-128 each)
    #pragma unroll
    for (int q = 0; q < 2; q++) {
        int j   = tid + q * THR3;
        int seg = j >> 5, hd = j & (HID - 1);
        float acc = 0.f;
        const float* pr = s_pool + seg * CHAN;
        const float* wr = W1 + hd * CHAN;
        #pragma unroll 8
        for (int k = 0; k < CHAN; k++)
            acc += pr[k] * __ldg(wr + k);
        s_h[j] = fmaxf(acc, 0.f);
    }
    __syncthreads();

    // gate: 2048 values, 8 per thread (dot-32 each)
    #pragma unroll
    for (int q = 0; q < 8; q++) {
        int j   = tid + q * THR3;
        int seg = j >> 7, c = j & (CHAN - 1);
        float acc = 0.f;
        const float* hr = s_h + seg * HID;
        const float* wr = W2 + c * HID;
        #pragma unroll
        for (int k = 0; k < HID; k++)
            acc += hr[k] * __ldg(wr + k);
        s_gatef[j] = 1.0f / (1.0f + expf(-acc));
    }

    // --- ticket: after this barrier all g_sum/g_cnt loads are consumed ---
    __syncthreads();
    if (tid == 0) s_last = atomicAdd(&g_ticket, 1);
    __syncthreads();
    if (s_last == NBLK3 - 1) {
        // last block: restore zero invariant for the next graph replay
        for (int i = tid; i < NUM_SEG * CHAN; i += THR3) g_sum[i] = 0.f;
        if (tid < NUM_SEG) g_cnt[tid] = 0.f;
        if (tid == 0) g_ticket = 0;
    }

    // --- streaming modulate ---
    const F4* s_gate = (const F4*)s_gatef;   // [seg*32 + lane] float4 view
    const float4* X = (const float4*)x;
    float4* O = (float4*)out;
    const int total  = N * 32;
    const int stride = NBLK3 * THR3;

    #pragma unroll 4
    for (int i = blockIdx.x * THR3 + tid; i < total; i += stride) {
        int row  = i >> 5;
        int lane = i & 31;
        int s = __ldg(idx + row);
        float4 v = __ldcs(X + i);
        F4 g = s_gate[s * 32 + lane];
        unsigned long long* vp = (unsigned long long*)&v;
        vp[0] = fmul2(vp[0], g.lo);
        vp[1] = fmul2(vp[1], g.hi);
        __stcs(O + i, v);
    }
}

// ---------------------------------------------------------------------------
extern "C" void kernel_launch(void* const* d_in, const int* in_sizes, int n_in,
                              void* d_out, int out_size)
{
    const float* x   = (const float*)d_in[0];
    const int*   idx = (const int*)d_in[1];
    const float* W1  = (const float*)d_in[2];
    const float* W2  = (const float*)d_in[3];
    float* out = (float*)d_out;

    const int N = in_sizes[1];  // number of points

    seg_sum_kernel<<<NBLK1, THR1>>>(x, idx, N);
    modulate_kernel<<<NBLK3, THR3>>>(x, idx, W1, W2, out, N);
}

// round 13
// speedup vs baseline: 2.7993x; 2.7993x over previous
#include <cuda_runtime.h>
#include <cuda_bf16.h>
#include <math.h>

#define NUM_SEG 16
#define CHAN 128
#define HID 32

// Pass-1: 128 thr (4 warps), ~33KB smem -> 6 blocks/SM. Single full wave.
#define NBLK1 888          // 148 SMs * 6 blocks
#define THR1 128

// Modulate: 8 blocks/SM single wave
#define NBLK3 1184
#define THR3 256

// Zero-initialized at module load; reduce_mlp re-zeroes after consuming, so
// the zero invariant holds across every graph replay (same work every call).
__device__ float g_sum[NUM_SEG * CHAN];   // atomic accumulators
__device__ float g_cnt[NUM_SEG];          // atomic count accumulators
__device__ float g_gate[NUM_SEG * CHAN];  // final gates

// ---- packed f32x2 helpers (sm_103a) --------------------------------------
__device__ __forceinline__ unsigned long long fadd2(unsigned long long a,
                                                    unsigned long long b) {
    unsigned long long r;
    asm("add.rn.f32x2 %0, %1, %2;" : "=l"(r) : "l"(a), "l"(b));
    return r;
}
__device__ __forceinline__ unsigned long long fmul2(unsigned long long a,
                                                    unsigned long long b) {
    unsigned long long r;
    asm("mul.rn.f32x2 %0, %1, %2;" : "=l"(r) : "l"(a), "l"(b));
    return r;
}

struct F4 { unsigned long long lo, hi; };  // float4 as 2x f32x2

__device__ __forceinline__ F4 ld_f4_cs(const F4* p) {
    F4 r;
    asm("ld.global.cs.v4.b32 {%0,%1,%2,%3}, [%4];"
        : "=r"(((unsigned*)&r)[0]), "=r"(((unsigned*)&r)[1]),
          "=r"(((unsigned*)&r)[2]), "=r"(((unsigned*)&r)[3])
        : "l"(p));
    return r;
}

__device__ __forceinline__ void rmw(F4* buf, int s, int lane, F4 v) {
    F4* p = buf + s * 32 + lane;
    F4 a = *p;
    a.lo = fadd2(a.lo, v.lo);
    a.hi = fadd2(a.hi, v.hi);
    *p = a;
}

// ---------------------------------------------------------------------------
// Kernel 1: segment sums (at its L1tex/DRAM co-limit ~12 wf/row). Epilogue:
// combine the 4 warp-private regions, then RED (atomicAdd, no return) the
// 2048 floats straight into g_sum — no partial buffer round-trip.
// ---------------------------------------------------------------------------
__global__ void __launch_bounds__(THR1) seg_sum_kernel(
    const float* __restrict__ x, const int* __restrict__ idx, int N)
{
    __shared__ F4 s_acc[4 * NUM_SEG * 32];   // 32KB
    __shared__ float s_cnt[4 * NUM_SEG];

    const int tid  = threadIdx.x;
    const int lane = tid & 31;
    const int w    = tid >> 5;

    F4* buf = s_acc + w * (NUM_SEG * 32);

    for (int i = tid; i < 4 * NUM_SEG * 32; i += THR1) {
        s_acc[i].lo = 0ull; s_acc[i].hi = 0ull;
    }
    __syncthreads();

    const int gw = blockIdx.x * 4 + w;   // global warp id
    const int NW = NBLK1 * 4;            // total warps
    const F4* X = (const F4*)x;
    const int ngroups = N >> 3;          // groups of 8 rows

    int cnt = 0;
    for (int g = gw; g < ngroups; g += NW) {
        const int base = g << 3;
        int4 i0 = __ldg((const int4*)(idx + base));
        int4 i1 = __ldg((const int4*)(idx + base + 4));
        const size_t o = (size_t)base * 32 + lane;
        F4 v0 = ld_f4_cs(X + o);
        F4 v1 = ld_f4_cs(X + o + 32);
        F4 v2 = ld_f4_cs(X + o + 64);
        F4 v3 = ld_f4_cs(X + o + 96);
        F4 v4 = ld_f4_cs(X + o + 128);
        F4 v5 = ld_f4_cs(X + o + 160);
        F4 v6 = ld_f4_cs(X + o + 192);
        F4 v7 = ld_f4_cs(X + o + 224);

        cnt += (i0.x == lane) + (i0.y == lane) + (i0.z == lane) + (i0.w == lane)
             + (i1.x == lane) + (i1.y == lane) + (i1.z == lane) + (i1.w == lane);

        rmw(buf, i0.x, lane, v0);
        rmw(buf, i0.y, lane, v1);
        rmw(buf, i0.z, lane, v2);
        rmw(buf, i0.w, lane, v3);
        rmw(buf, i1.x, lane, v4);
        rmw(buf, i1.y, lane, v5);
        rmw(buf, i1.z, lane, v6);
        rmw(buf, i1.w, lane, v7);
    }
    // tail (N not multiple of 8)
    for (int r = (ngroups << 3) + gw; r < N; r += NW) {
        int s = __ldg(idx + r);
        F4 v = ld_f4_cs(X + (size_t)r * 32 + lane);
        cnt += (s == lane);
        rmw(buf, s, lane, v);
    }

    if (lane < NUM_SEG) s_cnt[w * NUM_SEG + lane] = (float)cnt;
    __syncthreads();

    // Combine 4 warp regions -> RED into g_sum (layout [seg*128 + chan]).
    const float* sa = (const float*)s_acc;
    const int R = NUM_SEG * CHAN;  // 2048 floats per region
    #pragma unroll 4
    for (int i = tid; i < R; i += THR1) {
        float v = sa[i] + sa[R + i] + sa[2 * R + i] + sa[3 * R + i];
        atomicAdd(&g_sum[i], v);
    }
    if (tid < NUM_SEG) {
        float c = s_cnt[tid] + s_cnt[NUM_SEG + tid] +
                  s_cnt[2 * NUM_SEG + tid] + s_cnt[3 * NUM_SEG + tid];
        atomicAdd(&g_cnt[tid], c);
    }
}

// ---------------------------------------------------------------------------
// Kernel 2: SE MLP on the accumulated sums (8KB read), then RE-ZERO the
// accumulators (replay invariant). PDL: launched early, syncs on seg_sum
// completion before reading g_sum/g_cnt. 16 blocks x 128 threads.
// ---------------------------------------------------------------------------
__global__ void __launch_bounds__(CHAN) reduce_mlp_kernel(
    const float* __restrict__ W1, const float* __restrict__ W2)
{
    cudaGridDependencySynchronize();   // wait for seg_sum's memory

    const int s = blockIdx.x;
    const int c = threadIdx.x;

    __shared__ float s_pooled[CHAN];
    __shared__ float s_h[HID];

    float cnt = fmaxf(g_cnt[s], 1.0f);
    s_pooled[c] = g_sum[s * CHAN + c] / cnt;
    __syncthreads();

    // g_sum/g_cnt fully consumed above -> restore zero invariant now.
    g_sum[s * CHAN + c] = 0.f;
    if (c == 0) g_cnt[s] = 0.f;

    if (c < HID) {
        float acc = 0.f;
        #pragma unroll 8
        for (int k = 0; k < CHAN; k++)
            acc += s_pooled[k] * __ldg(W1 + c * CHAN + k);
        s_h[c] = fmaxf(acc, 0.f);
    }
    __syncthreads();

    float acc = 0.f;
    #pragma unroll
    for (int k = 0; k < HID; k++)
        acc += s_h[k] * __ldg(W2 + c * HID + k);
    g_gate[s * CHAN + c] = 1.0f / (1.0f + expf(-acc));
}

// ---------------------------------------------------------------------------
// Kernel 3: out = x * gate[idx] (measured at the mixed R/W DRAM cap).
// PDL: launched early, syncs on reduce_mlp before reading g_gate.
// ---------------------------------------------------------------------------
__global__ void __launch_bounds__(THR3) modulate_kernel(
    const float* __restrict__ x, const int* __restrict__ idx,
    float* __restrict__ out, int N)
{
    cudaGridDependencySynchronize();   // wait for reduce_mlp's g_gate

    __shared__ float4 s_gate[NUM_SEG * 32];  // 8KB

    for (int i = threadIdx.x; i < NUM_SEG * 32; i += THR3)
        s_gate[i] = ((const float4*)g_gate)[i];
    __syncthreads();

    const float4* X = (const float4*)x;
    float4* O = (float4*)out;
    const int total  = N * 32;
    const int stride = NBLK3 * THR3;

    #pragma unroll 4
    for (int i = blockIdx.x * THR3 + threadIdx.x; i < total; i += stride) {
        int row  = i >> 5;
        int lane = i & 31;
        int s = __ldg(idx + row);
        float4 v = __ldcs(X + i);
        float4 g = s_gate[s * 32 + lane];
        unsigned long long* vp = (unsigned long long*)&v;
        const unsigned long long* gp = (const unsigned long long*)&g;
        vp[0] = fmul2(vp[0], gp[0]);
        vp[1] = fmul2(vp[1], gp[1]);
        __stcs(O + i, v);
    }
}

// ---------------------------------------------------------------------------
extern "C" void kernel_launch(void* const* d_in, const int* in_sizes, int n_in,
                              void* d_out, int out_size)
{
    const float* x   = (const float*)d_in[0];
    const int*   idx = (const int*)d_in[1];
    const float* W1  = (const float*)d_in[2];
    const float* W2  = (const float*)d_in[3];
    float* out = (float*)d_out;

    const int N = in_sizes[1];  // number of points

    seg_sum_kernel<<<NBLK1, THR1>>>(x, idx, N);

    // PDL launches: overlap launch latency with predecessor's drain.
    cudaLaunchAttribute attr[1];
    attr[0].id = cudaLaunchAttributeProgrammaticStreamSerialization;
    attr[0].val.programmaticStreamSerializationAllowed = 1;

    {
        cudaLaunchConfig_t cfg = {};
        cfg.gridDim  = dim3(NUM_SEG, 1, 1);
        cfg.blockDim = dim3(CHAN, 1, 1);
        cfg.attrs = attr;
        cfg.numAttrs = 1;
        cudaLaunchKernelEx(&cfg, reduce_mlp_kernel, W1, W2);
    }
    {
        cudaLaunchConfig_t cfg = {};
        cfg.gridDim  = dim3(NBLK3, 1, 1);
        cfg.blockDim = dim3(THR3, 1, 1);
        cfg.attrs = attr;
        cfg.numAttrs = 1;
        cudaLaunchKernelEx(&cfg, modulate_kernel, x, idx, out, N);
    }
}